// round 4
// baseline (speedup 1.0000x reference)
#include <cuda_runtime.h>
#include <math.h>
#include <limits.h>

#define NSIG 5
#define NROWS 10
#define SIG_LEN 2097152
#define HALF 5
#define THREADS 256
#define EPT 8
#define TILE (THREADS*EPT)        /* 2048 */
#define CHUNKS (SIG_LEN/TILE)     /* 1024 */
#define CAP 384                   /* peak slots per chunk (hard max 342: spacing >=6) */
#define KPL (CAP/32)              /* 12 entries per lane in pass2 */
#define WPB 8                     /* warps (chunks) per pass2 block */
#define FULLM 0xFFFFFFFFu

struct __align__(16) P1Rec { float s; float ps; int c; int pad; };

__device__ P1Rec d_p1[NROWS*CHUNKS];
__device__ float d_thr[NROWS];
__device__ int2 d_pk[(size_t)NROWS*CHUNKS*CAP];   /* compact peak lists */
__device__ int d_cnt[NROWS*CHUNKS];
__device__ unsigned long long d_inv[NROWS];        /* fixed-point sum of 1/gap */
__device__ unsigned long long d_pairs[NROWS];

static __device__ __forceinline__ float neg_inf() { return __int_as_float(0xff800000); }

// round(2^42 / gap) — integer fixed point so atomic order never changes the result
static __device__ __forceinline__ long long fixinv(int gap){
  return __double2ll_rn(4398046511104.0 / (double)gap);
}

__device__ __forceinline__ const float* row_ptr(const float* rppg, const float* ppg, int s){
  return (s < NSIG) ? rppg + (size_t)s*SIG_LEN : ppg + (size_t)(s-NSIG)*SIG_LEN;
}

// Load v[0..17] = x[p0-5 .. p0+12] (thread owns outputs p0..p0+7).
__device__ __forceinline__ void load_vals(const float* __restrict__ x, int p0, float* v){
  float4 a = *reinterpret_cast<const float4*>(x + p0);
  float4 b = *reinterpret_cast<const float4*>(x + p0 + 4);
  v[5]=a.x; v[6]=a.y; v[7]=a.z; v[8]=a.w;
  v[9]=b.x; v[10]=b.y; v[11]=b.z; v[12]=b.w;
  v[0]  = __shfl_up_sync(FULLM, v[8], 1);
  v[1]  = __shfl_up_sync(FULLM, v[9], 1);
  v[2]  = __shfl_up_sync(FULLM, v[10], 1);
  v[3]  = __shfl_up_sync(FULLM, v[11], 1);
  v[4]  = __shfl_up_sync(FULLM, v[12], 1);
  v[13] = __shfl_down_sync(FULLM, v[5], 1);
  v[14] = __shfl_down_sync(FULLM, v[6], 1);
  v[15] = __shfl_down_sync(FULLM, v[7], 1);
  v[16] = __shfl_down_sync(FULLM, v[8], 1);
  v[17] = __shfl_down_sync(FULLM, v[9], 1);
  int lane = threadIdx.x & 31;
  if (lane == 0) {
    #pragma unroll
    for (int k = 0; k < HALF; k++) {
      int g = p0 - HALF + k;
      v[k] = (g >= 0) ? __ldg(x + g) : neg_inf();
    }
  }
  if (lane == 31) {
    #pragma unroll
    for (int k = 0; k < HALF; k++) {
      int g = p0 + EPT + k;
      v[13+k] = (g < SIG_LEN) ? __ldg(x + g) : neg_inf();
    }
  }
}

// Centered width-11 sliding max, register max-tree.
__device__ __forceinline__ void window_max(const float* v, float* w){
  float a2[17];
  #pragma unroll
  for (int i = 0; i < 17; i++) a2[i] = fmaxf(v[i], v[i+1]);
  float a4[15];
  #pragma unroll
  for (int i = 0; i < 15; i++) a4[i] = fmaxf(a2[i], a2[i+2]);
  float a8[11];
  #pragma unroll
  for (int i = 0; i < 11; i++) a8[i] = fmaxf(a4[i], a4[i+4]);
  #pragma unroll
  for (int i = 0; i < EPT; i++) w[i] = fmaxf(a8[i], a8[i+3]);
}

// Pass 1: per-chunk stats AND compact peak list (peak mask is thr-independent).
__global__ void __launch_bounds__(THREADS) k_pass1(const float* __restrict__ rppg,
                                                   const float* __restrict__ ppg){
  int s = blockIdx.y;
  const float* __restrict__ x = row_ptr(rppg, ppg, s);
  int tid = threadIdx.x, lane = tid & 31, wid = tid >> 5;
  int p0 = blockIdx.x * TILE + tid * EPT;
  float v[18]; load_vals(x, p0, v);
  float w[EPT]; window_max(v, w);
  float lsum = 0.f, lps = 0.f; int lc = 0;
  int ppos[4]; float pval[4]; int np = 0;   // min peak spacing 6 -> <=2 per 8 elems
  #pragma unroll
  for (int i = 0; i < EPT; i++) {
    float c = v[i + HALF];
    lsum += c;
    if (c == w[i]) {
      lps += c; lc++;
      if (np < 4) { ppos[np] = p0 + i; pval[np] = c; np++; }
    }
  }
  // block-wide exclusive prefix of np
  int inc = np;
  #pragma unroll
  for (int off = 1; off < 32; off <<= 1) {
    int t = __shfl_up_sync(FULLM, inc, off);
    if (lane >= off) inc += t;
  }
  int exc = inc - np;
  __shared__ int wsum[8]; __shared__ int wbase[9];
  if (lane == 31) wsum[wid] = inc;
  __syncthreads();
  if (tid == 0) {
    int b = 0;
    #pragma unroll
    for (int ww = 0; ww < 8; ww++) { wbase[ww] = b; b += wsum[ww]; }
    wbase[8] = b;
  }
  __syncthreads();
  int base = wbase[wid] + exc;
  size_t cbase = (size_t)(s*CHUNKS + blockIdx.x) * CAP;
  for (int j = 0; j < np; j++) {
    int slot = base + j;
    if (slot < CAP) d_pk[cbase + slot] = make_int2(ppos[j], __float_as_int(pval[j]));
  }
  if (tid == 0) d_cnt[s*CHUNKS + blockIdx.x] = min(wbase[8], CAP);
  // stats reduction
  #pragma unroll
  for (int off = 16; off > 0; off >>= 1) {
    lsum += __shfl_down_sync(FULLM, lsum, off);
    lps  += __shfl_down_sync(FULLM, lps, off);
    lc   += __shfl_down_sync(FULLM, lc, off);
  }
  __shared__ float sA[8]; __shared__ float sB[8]; __shared__ int sC[8];
  if (lane == 0) { sA[wid] = lsum; sB[wid] = lps; sC[wid] = lc; }
  __syncthreads();
  if (wid == 0 && lane < 8) {
    float a = sA[lane], b = sB[lane]; int c = sC[lane];
    #pragma unroll
    for (int off = 4; off > 0; off >>= 1) {
      a += __shfl_down_sync(0xFF, a, off);
      b += __shfl_down_sync(0xFF, b, off);
      c += __shfl_down_sync(0xFF, c, off);
    }
    if (lane == 0) {
      P1Rec r; r.s = a; r.ps = b; r.c = c; r.pad = 0;
      d_p1[s*CHUNKS + blockIdx.x] = r;
    }
  }
}

// Per-row reduction of pass-1 partials -> threshold; also zero the row accumulators.
__global__ void __launch_bounds__(THREADS) k_thr(){
  int s = blockIdx.x; int tid = threadIdx.x, lane = tid & 31, wid = tid >> 5;
  if (tid == 0) { d_inv[s] = 0ull; d_pairs[s] = 0ull; }
  double ls = 0.0, lps = 0.0; long long lc = 0;
  for (int c = tid; c < CHUNKS; c += THREADS) {
    P1Rec r = d_p1[s*CHUNKS + c];
    ls += (double)r.s; lps += (double)r.ps; lc += r.c;
  }
  #pragma unroll
  for (int off = 16; off > 0; off >>= 1) {
    ls  += __shfl_down_sync(FULLM, ls, off);
    lps += __shfl_down_sync(FULLM, lps, off);
    lc  += __shfl_down_sync(FULLM, lc, off);
  }
  __shared__ double sA[8]; __shared__ double sB[8]; __shared__ long long sC[8];
  if (lane == 0) { sA[wid] = ls; sB[wid] = lps; sC[wid] = lc; }
  __syncthreads();
  if (wid == 0 && lane < 8) {
    double a = sA[lane], b = sB[lane]; long long c = sC[lane];
    #pragma unroll
    for (int off = 4; off > 0; off >>= 1) {
      a += __shfl_down_sync(0xFF, a, off);
      b += __shfl_down_sync(0xFF, b, off);
      c += __shfl_down_sync(0xFF, c, off);
    }
    if (lane == 0) {
      double mu = a / (double)SIG_LEN;
      double mp = b / (double)c;
      d_thr[s] = (float)(0.5 * (mp + mu));
    }
  }
}

// Pass 2: 8 warps/block, one chunk per warp. Boundary pair found by backward
// probe of previous chunks' lists. Row totals via deterministic integer atomics.
__global__ void __launch_bounds__(THREADS) k_pass2(){
  int s = blockIdx.y;
  int tid = threadIdx.x, lane = tid & 31, wid = tid >> 5;
  int c = blockIdx.x * WPB + wid;
  int rowb = s * CHUNKS;
  float thr = d_thr[s];
  int n = d_cnt[rowb + c];
  const int2* __restrict__ pk = d_pk + (size_t)(rowb + c) * CAP;
  long long linv = 0; int lpairs = 0; int lfirst = -1, lprev = -1;
  int e0 = lane * KPL;
  #pragma unroll
  for (int j = 0; j < KPL; j++) {
    int e = e0 + j;
    if (e < n) {
      int2 r = pk[e];
      if (__int_as_float(r.y) > thr) {
        if (lprev >= 0) { linv += fixinv(r.x - lprev); lpairs++; }
        else lfirst = r.x;
        lprev = r.x;
      }
    }
  }
  // warp inclusive max-scan of lprev -> predecessor for each lane's first peak
  int inc = lprev;
  #pragma unroll
  for (int off = 1; off < 32; off <<= 1) {
    int t = __shfl_up_sync(FULLM, inc, off);
    if (lane >= off) inc = max(inc, t);
  }
  int exprev = __shfl_up_sync(FULLM, inc, 1);
  if (lane == 0) exprev = -1;
  if (lfirst >= 0 && exprev >= 0) { linv += fixinv(lfirst - exprev); lpairs++; }
  // reduce within warp (result on all lanes)
  int firstv = (lfirst >= 0) ? lfirst : INT_MAX;
  #pragma unroll
  for (int off = 16; off > 0; off >>= 1) {
    linv   += __shfl_xor_sync(FULLM, linv, off);
    lpairs += __shfl_xor_sync(FULLM, lpairs, off);
    firstv  = min(firstv, __shfl_xor_sync(FULLM, firstv, off));
  }
  // backward probe: last filtered peak strictly before this chunk
  int prevg = -1;
  if (c > 0 && firstv != INT_MAX) {
    for (int pc = c - 1; pc >= 0; pc--) {
      int pn = d_cnt[rowb + pc];
      const int2* __restrict__ pp = d_pk + (size_t)(rowb + pc) * CAP;
      for (int base = ((pn - 1) >> 5) << 5; base >= 0; base -= 32) {
        int e = base + lane; int cand = -1;
        if (e < pn) {
          int2 r = pp[e];
          if (__int_as_float(r.y) > thr) cand = r.x;
        }
        #pragma unroll
        for (int off = 16; off > 0; off >>= 1)
          cand = max(cand, __shfl_xor_sync(FULLM, cand, off));
        if (cand >= 0) { prevg = cand; break; }
      }
      if (prevg >= 0) break;
    }
  }
  long long winv = linv; int wpairs = lpairs;
  if (firstv != INT_MAX && prevg >= 0) { winv += fixinv(firstv - prevg); wpairs++; }
  // block aggregation -> one atomic pair per block
  __shared__ long long sInv[WPB]; __shared__ int sPr[WPB];
  if (lane == 0) { sInv[wid] = winv; sPr[wid] = wpairs; }
  __syncthreads();
  if (tid == 0) {
    long long ti = 0; int tp = 0;
    #pragma unroll
    for (int ww = 0; ww < WPB; ww++) { ti += sInv[ww]; tp += sPr[ww]; }
    atomicAdd(&d_inv[s], (unsigned long long)ti);
    atomicAdd(&d_pairs[s], (unsigned long long)tp);
  }
}

// Combine rows; 60*fs/2^42 scale cancels in the ratio.
__global__ void k_final(float* __restrict__ out){
  if (threadIdx.x == 0) {
    double acc = 0.0;
    #pragma unroll
    for (int i = 0; i < NSIG; i++) {
      double hp = (double)d_inv[NSIG + i] / (double)d_pairs[NSIG + i];  // ppg
      double hq = (double)d_inv[i]        / (double)d_pairs[i];        // rppg
      acc += fabs(hp - hq) / hp;
    }
    out[0] = (float)(acc / (double)NSIG);
  }
}

extern "C" void kernel_launch(void* const* d_in, const int* in_sizes, int n_in,
                              void* d_out, int out_size){
  (void)in_sizes; (void)n_in; (void)out_size;
  const float* rppg = (const float*)d_in[0];
  const float* ppg  = (const float*)d_in[1];
  float* out = (float*)d_out;
  dim3 g1(CHUNKS, NROWS);
  dim3 g2(CHUNKS/WPB, NROWS);
  k_pass1<<<g1, THREADS>>>(rppg, ppg);
  k_thr<<<NROWS, THREADS>>>();
  k_pass2<<<g2, THREADS>>>();
  k_final<<<1, 32>>>(out);
}

// round 5
// speedup vs baseline: 2.0368x; 2.0368x over previous
#include <cuda_runtime.h>
#include <math.h>
#include <limits.h>

#define NSIG 5
#define NROWS 10
#define SIG_LEN 2097152
#define HALF 5
#define THREADS 256
#define EPT 8
#define TILE (THREADS*EPT)        /* 2048 */
#define CHUNKS (SIG_LEN/TILE)     /* 1024 */
#define RPT (CHUNKS/THREADS)      /* 4 */
#define CAP 384                   /* peak slots per chunk (hard max 342) */
#define KPL (CAP/32)              /* 12 entries per lane in pass2 */
#define WPB 8                     /* chunks per pass2 block */
#define P2B (CHUNKS/WPB)          /* 128 pass2 blocks per row */
#define FULLM 0xFFFFFFFFu

struct __align__(16) P1Rec { float s; float ps; int c; int pad; };
struct __align__(16) ChunkRec { int first; int last; float inv; int pairs; };

__device__ P1Rec d_p1[NROWS*CHUNKS];
__device__ float d_thr[NROWS];
__device__ int2 d_pk[(size_t)NROWS*CHUNKS*CAP];
__device__ int d_cnt[NROWS*CHUNKS];
__device__ ChunkRec d_rec[NROWS*CHUNKS];
__device__ double d_hr[NROWS];
__device__ int d_c1[NROWS];       /* zero-init; self-resetting */
__device__ int d_c2[NROWS];
__device__ int d_rows;

static __device__ __forceinline__ float neg_inf() { return __int_as_float(0xff800000); }

__device__ __forceinline__ const float* row_ptr(const float* rppg, const float* ppg, int s){
  return (s < NSIG) ? rppg + (size_t)s*SIG_LEN : ppg + (size_t)(s-NSIG)*SIG_LEN;
}

__device__ __forceinline__ void load_vals(const float* __restrict__ x, int p0, float* v){
  float4 a = *reinterpret_cast<const float4*>(x + p0);
  float4 b = *reinterpret_cast<const float4*>(x + p0 + 4);
  v[5]=a.x; v[6]=a.y; v[7]=a.z; v[8]=a.w;
  v[9]=b.x; v[10]=b.y; v[11]=b.z; v[12]=b.w;
  v[0]  = __shfl_up_sync(FULLM, v[8], 1);
  v[1]  = __shfl_up_sync(FULLM, v[9], 1);
  v[2]  = __shfl_up_sync(FULLM, v[10], 1);
  v[3]  = __shfl_up_sync(FULLM, v[11], 1);
  v[4]  = __shfl_up_sync(FULLM, v[12], 1);
  v[13] = __shfl_down_sync(FULLM, v[5], 1);
  v[14] = __shfl_down_sync(FULLM, v[6], 1);
  v[15] = __shfl_down_sync(FULLM, v[7], 1);
  v[16] = __shfl_down_sync(FULLM, v[8], 1);
  v[17] = __shfl_down_sync(FULLM, v[9], 1);
  int lane = threadIdx.x & 31;
  if (lane == 0) {
    #pragma unroll
    for (int k = 0; k < HALF; k++) {
      int g = p0 - HALF + k;
      v[k] = (g >= 0) ? __ldg(x + g) : neg_inf();
    }
  }
  if (lane == 31) {
    #pragma unroll
    for (int k = 0; k < HALF; k++) {
      int g = p0 + EPT + k;
      v[13+k] = (g < SIG_LEN) ? __ldg(x + g) : neg_inf();
    }
  }
}

__device__ __forceinline__ void window_max(const float* v, float* w){
  float a2[17];
  #pragma unroll
  for (int i = 0; i < 17; i++) a2[i] = fmaxf(v[i], v[i+1]);
  float a4[15];
  #pragma unroll
  for (int i = 0; i < 15; i++) a4[i] = fmaxf(a2[i], a2[i+2]);
  float a8[11];
  #pragma unroll
  for (int i = 0; i < 11; i++) a8[i] = fmaxf(a4[i], a4[i+4]);
  #pragma unroll
  for (int i = 0; i < EPT; i++) w[i] = fmaxf(a8[i], a8[i+3]);
}

// k1 = pass1 (stats + compact peak lists) + last-block-per-row threshold.
__global__ void __launch_bounds__(THREADS) k1(const float* __restrict__ rppg,
                                              const float* __restrict__ ppg){
  int s = blockIdx.y;
  const float* __restrict__ x = row_ptr(rppg, ppg, s);
  int tid = threadIdx.x, lane = tid & 31, wid = tid >> 5;
  int p0 = blockIdx.x * TILE + tid * EPT;
  float v[18]; load_vals(x, p0, v);
  float w[EPT]; window_max(v, w);
  float lsum = 0.f, lps = 0.f; int lc = 0;
  int ppos[4]; float pval[4]; int np = 0;
  #pragma unroll
  for (int i = 0; i < EPT; i++) {
    float c = v[i + HALF];
    lsum += c;
    if (c == w[i]) {
      lps += c; lc++;
      if (np < 4) { ppos[np] = p0 + i; pval[np] = c; np++; }
    }
  }
  // compact peak list
  int inc = np;
  #pragma unroll
  for (int off = 1; off < 32; off <<= 1) {
    int t = __shfl_up_sync(FULLM, inc, off);
    if (lane >= off) inc += t;
  }
  int exc = inc - np;
  __shared__ int wsum[8]; __shared__ int wbase[9];
  if (lane == 31) wsum[wid] = inc;
  __syncthreads();
  if (tid == 0) {
    int b = 0;
    #pragma unroll
    for (int ww = 0; ww < 8; ww++) { wbase[ww] = b; b += wsum[ww]; }
    wbase[8] = b;
  }
  __syncthreads();
  int base = wbase[wid] + exc;
  size_t cbase = (size_t)(s*CHUNKS + blockIdx.x) * CAP;
  for (int j = 0; j < np; j++) {
    int slot = base + j;
    if (slot < CAP) d_pk[cbase + slot] = make_int2(ppos[j], __float_as_int(pval[j]));
  }
  if (tid == 0) d_cnt[s*CHUNKS + blockIdx.x] = min(wbase[8], CAP);
  // stats reduction
  #pragma unroll
  for (int off = 16; off > 0; off >>= 1) {
    lsum += __shfl_down_sync(FULLM, lsum, off);
    lps  += __shfl_down_sync(FULLM, lps, off);
    lc   += __shfl_down_sync(FULLM, lc, off);
  }
  __shared__ float sA[8]; __shared__ float sB[8]; __shared__ int sC[8];
  if (lane == 0) { sA[wid] = lsum; sB[wid] = lps; sC[wid] = lc; }
  __syncthreads();
  if (tid == 0) {
    float a = 0.f, b = 0.f; int c = 0;
    #pragma unroll
    for (int ww = 0; ww < 8; ww++) { a += sA[ww]; b += sB[ww]; c += sC[ww]; }
    P1Rec r; r.s = a; r.ps = b; r.c = c; r.pad = 0;
    d_p1[s*CHUNKS + blockIdx.x] = r;
  }
  // last block of this row computes the threshold
  __shared__ int amLast;
  if (tid == 0) {
    __threadfence();
    amLast = (atomicAdd(&d_c1[s], 1) == CHUNKS - 1);
  }
  __syncthreads();
  if (amLast) {
    double ls = 0.0, lpsd = 0.0; long long lcc = 0;
    for (int c = tid; c < CHUNKS; c += THREADS) {
      P1Rec r = d_p1[s*CHUNKS + c];
      ls += (double)r.s; lpsd += (double)r.ps; lcc += r.c;
    }
    #pragma unroll
    for (int off = 16; off > 0; off >>= 1) {
      ls   += __shfl_down_sync(FULLM, ls, off);
      lpsd += __shfl_down_sync(FULLM, lpsd, off);
      lcc  += __shfl_down_sync(FULLM, lcc, off);
    }
    __shared__ double tA[8]; __shared__ double tB[8]; __shared__ long long tC[8];
    if (lane == 0) { tA[wid] = ls; tB[wid] = lpsd; tC[wid] = lcc; }
    __syncthreads();
    if (tid == 0) {
      double a = 0.0, b = 0.0; long long c = 0;
      #pragma unroll
      for (int ww = 0; ww < 8; ww++) { a += tA[ww]; b += tB[ww]; c += tC[ww]; }
      double mu = a / (double)SIG_LEN;
      double mp = b / (double)c;
      d_thr[s] = (float)(0.5 * (mp + mu));
      d_c1[s] = 0;   /* reset for next replay */
    }
  }
}

// k2 = pass2 (per-chunk gap sums, fp32) + last-block-per-row stitch + final.
__global__ void __launch_bounds__(THREADS) k2(float* __restrict__ out){
  int s = blockIdx.y;
  int tid = threadIdx.x, lane = tid & 31, wid = tid >> 5;
  int c = blockIdx.x * WPB + wid;
  int rowb = s * CHUNKS;
  float thr = d_thr[s];
  int n = d_cnt[rowb + c];
  const int2* __restrict__ pk = d_pk + (size_t)(rowb + c) * CAP;
  int lfirst = -1, lprev = -1, lpairs = 0; float linv = 0.f;
  int e0 = lane * KPL;
  #pragma unroll
  for (int j = 0; j < KPL; j++) {
    int e = e0 + j;
    if (e < n) {
      int2 r = pk[e];
      if (__int_as_float(r.y) > thr) {
        if (lprev >= 0) { linv += 1.0f / (float)(r.x - lprev); lpairs++; }
        else lfirst = r.x;
        lprev = r.x;
      }
    }
  }
  int inc = lprev;
  #pragma unroll
  for (int off = 1; off < 32; off <<= 1) {
    int t = __shfl_up_sync(FULLM, inc, off);
    if (lane >= off) inc = max(inc, t);
  }
  int exprev = __shfl_up_sync(FULLM, inc, 1);
  if (lane == 0) exprev = -1;
  int blast = __shfl_sync(FULLM, inc, 31);
  if (lfirst >= 0 && exprev >= 0) { linv += 1.0f / (float)(lfirst - exprev); lpairs++; }
  int firstv = (lfirst >= 0) ? lfirst : INT_MAX;
  #pragma unroll
  for (int off = 16; off > 0; off >>= 1) {
    linv   += __shfl_down_sync(FULLM, linv, off);
    lpairs += __shfl_down_sync(FULLM, lpairs, off);
    firstv  = min(firstv, __shfl_down_sync(FULLM, firstv, off));
  }
  if (lane == 0) {
    ChunkRec r;
    r.first = (firstv == INT_MAX) ? -1 : firstv;
    r.last  = blast;
    r.inv   = linv;
    r.pairs = lpairs;
    d_rec[rowb + c] = r;
  }
  // last block of this row stitches the row
  __shared__ int amLast;
  if (tid == 0) {
    __threadfence();
    amLast = (atomicAdd(&d_c2[s], 1) == P2B - 1);
  }
  __syncthreads();
  if (amLast) {
    const int4* rec = reinterpret_cast<const int4*>(d_rec) + (size_t)rowb + (size_t)tid * RPT;
    double sinv = 0.0; int spairs = 0; int sfirst = -1, sprev = -1;
    #pragma unroll
    for (int r = 0; r < RPT; r++) {
      int4 rv = rec[r];
      if (rv.x >= 0) {
        if (sprev >= 0) { sinv += 1.0 / (double)(rv.x - sprev); spairs++; }
        else sfirst = rv.x;
        sprev = rv.y;
      }
      sinv += (double)__int_as_float(rv.z);
      spairs += rv.w;
    }
    int inc2 = sprev;
    #pragma unroll
    for (int off = 1; off < 32; off <<= 1) {
      int t = __shfl_up_sync(FULLM, inc2, off);
      if (lane >= off) inc2 = max(inc2, t);
    }
    int exw = __shfl_up_sync(FULLM, inc2, 1);
    if (lane == 0) exw = -1;
    __shared__ int wmax[8];
    if (lane == 31) wmax[wid] = inc2;
    __syncthreads();
    int wpre = -1;
    for (int ww = 0; ww < wid; ww++) wpre = max(wpre, wmax[ww]);
    int exprev2 = max(exw, wpre);
    if (sfirst >= 0 && exprev2 >= 0) { sinv += 1.0 / (double)(sfirst - exprev2); spairs++; }
    #pragma unroll
    for (int off = 16; off > 0; off >>= 1) {
      sinv   += __shfl_down_sync(FULLM, sinv, off);
      spairs += __shfl_down_sync(FULLM, spairs, off);
    }
    __shared__ double sD[8]; __shared__ int sP[8];
    if (lane == 0) { sD[wid] = sinv; sP[wid] = spairs; }
    __syncthreads();
    if (tid == 0) {
      double dsum = 0.0; int psum = 0;
      #pragma unroll
      for (int ww = 0; ww < 8; ww++) { dsum += sD[ww]; psum += sP[ww]; }
      d_hr[s] = dsum / (double)psum;
      d_c2[s] = 0;  /* reset */
      __threadfence();
      if (atomicAdd(&d_rows, 1) == NROWS - 1) {
        double acc = 0.0;
        #pragma unroll
        for (int i = 0; i < NSIG; i++) {
          double hp = d_hr[NSIG + i];
          double hq = d_hr[i];
          acc += fabs(hp - hq) / hp;
        }
        out[0] = (float)(acc / (double)NSIG);
        d_rows = 0;  /* reset */
      }
    }
  }
}

extern "C" void kernel_launch(void* const* d_in, const int* in_sizes, int n_in,
                              void* d_out, int out_size){
  (void)in_sizes; (void)n_in; (void)out_size;
  const float* rppg = (const float*)d_in[0];
  const float* ppg  = (const float*)d_in[1];
  float* out = (float*)d_out;
  dim3 g1(CHUNKS, NROWS);
  dim3 g2(P2B, NROWS);
  k1<<<g1, THREADS>>>(rppg, ppg);
  k2<<<g2, THREADS>>>(out);
}

// round 6
// speedup vs baseline: 2.3860x; 1.1715x over previous
#include <cuda_runtime.h>
#include <math.h>
#include <limits.h>

#define NSIG 5
#define NROWS 10
#define SIG_LEN 2097152
#define HALF 5
#define THREADS 256
#define EPT 8
#define TILE (THREADS*EPT)        /* 2048 */
#define CHUNKS (SIG_LEN/TILE)     /* 1024 */
#define RPT (CHUNKS/THREADS)      /* 4 */
#define CAP 384                   /* peak slots per chunk (hard max 342) */
#define WPB 8                     /* chunks per pass2 block */
#define P2B (CHUNKS/WPB)          /* 128 pass2 blocks per row */
#define FULLM 0xFFFFFFFFu

struct __align__(16) P1Rec { float s; float ps; int c; int pad; };
struct __align__(16) ChunkRec { int first; int last; float inv; int pairs; };

__device__ P1Rec d_p1[NROWS*CHUNKS];
__device__ float d_thr[NROWS];
__device__ int2 d_pk[(size_t)NROWS*CHUNKS*CAP];
__device__ int d_cnt[NROWS*CHUNKS];
__device__ ChunkRec d_rec[NROWS*CHUNKS];
__device__ double d_hr[NROWS];
__device__ int d_c1[NROWS];       /* zero-init; self-resetting */
__device__ int d_c2[NROWS];
__device__ int d_rows;

static __device__ __forceinline__ float neg_inf() { return __int_as_float(0xff800000); }

__device__ __forceinline__ const float* row_ptr(const float* rppg, const float* ppg, int s){
  return (s < NSIG) ? rppg + (size_t)s*SIG_LEN : ppg + (size_t)(s-NSIG)*SIG_LEN;
}

__device__ __forceinline__ void load_vals(const float* __restrict__ x, int p0, float* v){
  float4 a = *reinterpret_cast<const float4*>(x + p0);
  float4 b = *reinterpret_cast<const float4*>(x + p0 + 4);
  v[5]=a.x; v[6]=a.y; v[7]=a.z; v[8]=a.w;
  v[9]=b.x; v[10]=b.y; v[11]=b.z; v[12]=b.w;
  v[0]  = __shfl_up_sync(FULLM, v[8], 1);
  v[1]  = __shfl_up_sync(FULLM, v[9], 1);
  v[2]  = __shfl_up_sync(FULLM, v[10], 1);
  v[3]  = __shfl_up_sync(FULLM, v[11], 1);
  v[4]  = __shfl_up_sync(FULLM, v[12], 1);
  v[13] = __shfl_down_sync(FULLM, v[5], 1);
  v[14] = __shfl_down_sync(FULLM, v[6], 1);
  v[15] = __shfl_down_sync(FULLM, v[7], 1);
  v[16] = __shfl_down_sync(FULLM, v[8], 1);
  v[17] = __shfl_down_sync(FULLM, v[9], 1);
  int lane = threadIdx.x & 31;
  if (lane == 0) {
    #pragma unroll
    for (int k = 0; k < HALF; k++) {
      int g = p0 - HALF + k;
      v[k] = (g >= 0) ? __ldg(x + g) : neg_inf();
    }
  }
  if (lane == 31) {
    #pragma unroll
    for (int k = 0; k < HALF; k++) {
      int g = p0 + EPT + k;
      v[13+k] = (g < SIG_LEN) ? __ldg(x + g) : neg_inf();
    }
  }
}

__device__ __forceinline__ void window_max(const float* v, float* w){
  float a2[17];
  #pragma unroll
  for (int i = 0; i < 17; i++) a2[i] = fmaxf(v[i], v[i+1]);
  float a4[15];
  #pragma unroll
  for (int i = 0; i < 15; i++) a4[i] = fmaxf(a2[i], a2[i+2]);
  float a8[11];
  #pragma unroll
  for (int i = 0; i < 11; i++) a8[i] = fmaxf(a4[i], a4[i+4]);
  #pragma unroll
  for (int i = 0; i < EPT; i++) w[i] = fmaxf(a8[i], a8[i+3]);
}

// k1 = pass1 (stats + compact peak lists; peaks >=6 apart -> <=2 per 8 elems,
// kept in two scalar register slots, no local memory) + last-block-per-row threshold.
__global__ void __launch_bounds__(THREADS) k1(const float* __restrict__ rppg,
                                              const float* __restrict__ ppg){
  int s = blockIdx.y;
  const float* __restrict__ x = row_ptr(rppg, ppg, s);
  int tid = threadIdx.x, lane = tid & 31, wid = tid >> 5;
  int p0 = blockIdx.x * TILE + tid * EPT;
  float v[18]; load_vals(x, p0, v);
  float w[EPT]; window_max(v, w);
  float lsum = 0.f, lps = 0.f; int lc = 0;
  int pa = -1, pb = -1; float va = 0.f, vb = 0.f;
  #pragma unroll
  for (int i = 0; i < EPT; i++) {
    float c = v[i + HALF];
    lsum += c;
    if (c == w[i]) {
      lps += c; lc++;
      if (pa < 0) { pa = p0 + i; va = c; }
      else        { pb = p0 + i; vb = c; }
    }
  }
  int np = (pa >= 0) + (pb >= 0);
  // block-wide exclusive prefix of np
  int inc = np;
  #pragma unroll
  for (int off = 1; off < 32; off <<= 1) {
    int t = __shfl_up_sync(FULLM, inc, off);
    if (lane >= off) inc += t;
  }
  int exc = inc - np;
  __shared__ int wsum[8]; __shared__ int wbase[9];
  if (lane == 31) wsum[wid] = inc;
  __syncthreads();
  if (tid == 0) {
    int b = 0;
    #pragma unroll
    for (int ww = 0; ww < 8; ww++) { wbase[ww] = b; b += wsum[ww]; }
    wbase[8] = b;
  }
  __syncthreads();
  int base = wbase[wid] + exc;
  size_t cbase = (size_t)(s*CHUNKS + blockIdx.x) * CAP;
  if (pa >= 0 && base     < CAP) d_pk[cbase + base]     = make_int2(pa, __float_as_int(va));
  if (pb >= 0 && base + 1 < CAP) d_pk[cbase + base + 1] = make_int2(pb, __float_as_int(vb));
  if (tid == 0) d_cnt[s*CHUNKS + blockIdx.x] = min(wbase[8], CAP);
  // stats reduction
  #pragma unroll
  for (int off = 16; off > 0; off >>= 1) {
    lsum += __shfl_down_sync(FULLM, lsum, off);
    lps  += __shfl_down_sync(FULLM, lps, off);
    lc   += __shfl_down_sync(FULLM, lc, off);
  }
  __shared__ float sA[8]; __shared__ float sB[8]; __shared__ int sC[8];
  if (lane == 0) { sA[wid] = lsum; sB[wid] = lps; sC[wid] = lc; }
  __syncthreads();
  if (tid == 0) {
    float a = 0.f, b = 0.f; int c = 0;
    #pragma unroll
    for (int ww = 0; ww < 8; ww++) { a += sA[ww]; b += sB[ww]; c += sC[ww]; }
    P1Rec r; r.s = a; r.ps = b; r.c = c; r.pad = 0;
    d_p1[s*CHUNKS + blockIdx.x] = r;
  }
  // last block of this row computes the threshold
  __shared__ int amLast;
  if (tid == 0) {
    __threadfence();
    amLast = (atomicAdd(&d_c1[s], 1) == CHUNKS - 1);
  }
  __syncthreads();
  if (amLast) {
    double ls = 0.0, lpsd = 0.0; long long lcc = 0;
    for (int c = tid; c < CHUNKS; c += THREADS) {
      P1Rec r = d_p1[s*CHUNKS + c];
      ls += (double)r.s; lpsd += (double)r.ps; lcc += r.c;
    }
    #pragma unroll
    for (int off = 16; off > 0; off >>= 1) {
      ls   += __shfl_down_sync(FULLM, ls, off);
      lpsd += __shfl_down_sync(FULLM, lpsd, off);
      lcc  += __shfl_down_sync(FULLM, lcc, off);
    }
    __shared__ double tA[8]; __shared__ double tB[8]; __shared__ long long tC[8];
    if (lane == 0) { tA[wid] = ls; tB[wid] = lpsd; tC[wid] = lcc; }
    __syncthreads();
    if (tid == 0) {
      double a = 0.0, b = 0.0; long long c = 0;
      #pragma unroll
      for (int ww = 0; ww < 8; ww++) { a += tA[ww]; b += tB[ww]; c += tC[ww]; }
      double mu = a / (double)SIG_LEN;
      double mp = b / (double)c;
      d_thr[s] = (float)(0.5 * (mp + mu));
      d_c1[s] = 0;
    }
  }
}

// k2 = pass2: warp-cooperative, coalesced batch loads + warp max-scan with carry.
__global__ void __launch_bounds__(THREADS) k2(float* __restrict__ out){
  int s = blockIdx.y;
  int tid = threadIdx.x, lane = tid & 31, wid = tid >> 5;
  int c = blockIdx.x * WPB + wid;
  int rowb = s * CHUNKS;
  float thr = d_thr[s];
  int n = d_cnt[rowb + c];
  const int2* __restrict__ pk = d_pk + (size_t)(rowb + c) * CAP;
  float linv = 0.f; int lpairs = 0; int lfirst = INT_MAX; int carry = -1;
  for (int base = 0; base < n; base += 32) {
    int e = base + lane;
    int pos = -1;
    if (e < n) {
      int2 r = pk[e];
      if (__int_as_float(r.y) > thr) pos = r.x;
    }
    int inc = pos;
    #pragma unroll
    for (int off = 1; off < 32; off <<= 1) {
      int t = __shfl_up_sync(FULLM, inc, off);
      if (lane >= off) inc = max(inc, t);
    }
    int ex = __shfl_up_sync(FULLM, inc, 1);
    if (lane == 0) ex = -1;
    int prev = max(ex, carry);
    if (pos >= 0) {
      if (prev >= 0) { linv += 1.0f / (float)(pos - prev); lpairs++; }
      else if (lfirst == INT_MAX) lfirst = pos;   // chunk's first filtered peak
    }
    carry = max(carry, __shfl_sync(FULLM, inc, 31));
  }
  int blast = carry;  // uniform across warp
  #pragma unroll
  for (int off = 16; off > 0; off >>= 1) {
    linv   += __shfl_down_sync(FULLM, linv, off);
    lpairs += __shfl_down_sync(FULLM, lpairs, off);
    lfirst  = min(lfirst, __shfl_down_sync(FULLM, lfirst, off));
  }
  if (lane == 0) {
    ChunkRec r;
    r.first = (lfirst == INT_MAX) ? -1 : lfirst;
    r.last  = blast;
    r.inv   = linv;
    r.pairs = lpairs;
    d_rec[rowb + c] = r;
  }
  // last block of this row stitches the row
  __shared__ int amLast;
  if (tid == 0) {
    __threadfence();
    amLast = (atomicAdd(&d_c2[s], 1) == P2B - 1);
  }
  __syncthreads();
  if (amLast) {
    const int4* rec = reinterpret_cast<const int4*>(d_rec) + (size_t)rowb + (size_t)tid * RPT;
    double sinv = 0.0; int spairs = 0; int sfirst = -1, sprev = -1;
    #pragma unroll
    for (int r = 0; r < RPT; r++) {
      int4 rv = rec[r];
      if (rv.x >= 0) {
        if (sprev >= 0) { sinv += 1.0 / (double)(rv.x - sprev); spairs++; }
        else sfirst = rv.x;
        sprev = rv.y;
      }
      sinv += (double)__int_as_float(rv.z);
      spairs += rv.w;
    }
    int inc2 = sprev;
    #pragma unroll
    for (int off = 1; off < 32; off <<= 1) {
      int t = __shfl_up_sync(FULLM, inc2, off);
      if (lane >= off) inc2 = max(inc2, t);
    }
    int exw = __shfl_up_sync(FULLM, inc2, 1);
    if (lane == 0) exw = -1;
    __shared__ int wmax[8];
    if (lane == 31) wmax[wid] = inc2;
    __syncthreads();
    int wpre = -1;
    for (int ww = 0; ww < wid; ww++) wpre = max(wpre, wmax[ww]);
    int exprev2 = max(exw, wpre);
    if (sfirst >= 0 && exprev2 >= 0) { sinv += 1.0 / (double)(sfirst - exprev2); spairs++; }
    #pragma unroll
    for (int off = 16; off > 0; off >>= 1) {
      sinv   += __shfl_down_sync(FULLM, sinv, off);
      spairs += __shfl_down_sync(FULLM, spairs, off);
    }
    __shared__ double sD[8]; __shared__ int sP[8];
    if (lane == 0) { sD[wid] = sinv; sP[wid] = spairs; }
    __syncthreads();
    if (tid == 0) {
      double dsum = 0.0; int psum = 0;
      #pragma unroll
      for (int ww = 0; ww < 8; ww++) { dsum += sD[ww]; psum += sP[ww]; }
      d_hr[s] = dsum / (double)psum;
      d_c2[s] = 0;
      __threadfence();
      if (atomicAdd(&d_rows, 1) == NROWS - 1) {
        double acc = 0.0;
        #pragma unroll
        for (int i = 0; i < NSIG; i++) {
          double hp = d_hr[NSIG + i];
          double hq = d_hr[i];
          acc += fabs(hp - hq) / hp;
        }
        out[0] = (float)(acc / (double)NSIG);
        d_rows = 0;
      }
    }
  }
}

extern "C" void kernel_launch(void* const* d_in, const int* in_sizes, int n_in,
                              void* d_out, int out_size){
  (void)in_sizes; (void)n_in; (void)out_size;
  const float* rppg = (const float*)d_in[0];
  const float* ppg  = (const float*)d_in[1];
  float* out = (float*)d_out;
  dim3 g1(CHUNKS, NROWS);
  dim3 g2(P2B, NROWS);
  k1<<<g1, THREADS>>>(rppg, ppg);
  k2<<<g2, THREADS>>>(out);
}

// round 9
// speedup vs baseline: 2.4784x; 1.0387x over previous
#include <cuda_runtime.h>
#include <math.h>
#include <limits.h>

#define NSIG 5
#define NROWS 10
#define SIG_LEN 2097152
#define HALF 5
#define THREADS 256
#define EPT 16
#define TILE (THREADS*EPT)        /* 4096 */
#define CHUNKS (SIG_LEN/TILE)     /* 512 */
#define RPT (CHUNKS/THREADS)      /* 2 */
#define CAP 704                   /* >= 683 distinct-value max + tie slack */
#define WPB 8                     /* chunks per pass2 block */
#define P2B (CHUNKS/WPB)          /* 64 pass2 blocks per row */
#define NV 26                     /* v[0..25] = x[p0-5 .. p0+20] */
#define FULLM 0xFFFFFFFFu

struct __align__(16) ChunkRec { int first; int last; float inv; int pairs; };

__device__ float2 d_p1[NROWS*CHUNKS];              /* {sum, peak-sum} per chunk */
__device__ float d_thr[NROWS];
__device__ int2 d_pk[(size_t)NROWS*CHUNKS*CAP];
__device__ int d_cnt[NROWS*CHUNKS];
__device__ ChunkRec d_rec[NROWS*CHUNKS];
__device__ double d_hr[NROWS];
__device__ int d_c1[NROWS];       /* zero-init; self-resetting */
__device__ int d_c2[NROWS];
__device__ int d_rows;

static __device__ __forceinline__ float neg_inf() { return __int_as_float(0xff800000); }

__device__ __forceinline__ const float* row_ptr(const float* rppg, const float* ppg, int s){
  return (s < NSIG) ? rppg + (size_t)s*SIG_LEN : ppg + (size_t)(s-NSIG)*SIG_LEN;
}

// v[5..20] = x[p0..p0+15]; halo v[0..4], v[21..25] via neighbor-lane shuffles.
__device__ __forceinline__ void load_vals(const float* __restrict__ x, int p0, float* v){
  #pragma unroll
  for (int q = 0; q < 4; q++) {
    float4 a = *reinterpret_cast<const float4*>(x + p0 + 4*q);
    v[5+4*q] = a.x; v[6+4*q] = a.y; v[7+4*q] = a.z; v[8+4*q] = a.w;
  }
  v[0]  = __shfl_up_sync(FULLM, v[16], 1);
  v[1]  = __shfl_up_sync(FULLM, v[17], 1);
  v[2]  = __shfl_up_sync(FULLM, v[18], 1);
  v[3]  = __shfl_up_sync(FULLM, v[19], 1);
  v[4]  = __shfl_up_sync(FULLM, v[20], 1);
  v[21] = __shfl_down_sync(FULLM, v[5], 1);
  v[22] = __shfl_down_sync(FULLM, v[6], 1);
  v[23] = __shfl_down_sync(FULLM, v[7], 1);
  v[24] = __shfl_down_sync(FULLM, v[8], 1);
  v[25] = __shfl_down_sync(FULLM, v[9], 1);
  int lane = threadIdx.x & 31;
  if (lane == 0) {
    #pragma unroll
    for (int k = 0; k < HALF; k++) {
      int g = p0 - HALF + k;
      v[k] = (g >= 0) ? __ldg(x + g) : neg_inf();
    }
  }
  if (lane == 31) {
    #pragma unroll
    for (int k = 0; k < HALF; k++) {
      int g = p0 + EPT + k;
      v[21+k] = (g < SIG_LEN) ? __ldg(x + g) : neg_inf();
    }
  }
}

// Centered width-11 sliding max for 16 outputs, register max-tree.
__device__ __forceinline__ void window_max(const float* v, float* w){
  float a2[NV-1];
  #pragma unroll
  for (int i = 0; i < NV-1; i++) a2[i] = fmaxf(v[i], v[i+1]);
  float a4[NV-3];
  #pragma unroll
  for (int i = 0; i < NV-3; i++) a4[i] = fmaxf(a2[i], a2[i+2]);
  float a8[NV-7];
  #pragma unroll
  for (int i = 0; i < NV-7; i++) a8[i] = fmaxf(a4[i], a4[i+4]);
  #pragma unroll
  for (int i = 0; i < EPT; i++) w[i] = fmaxf(a8[i], a8[i+3]);  // v[i..i+10]
}

// k1 = pass1 (stats + compact peak lists; 4 scalar slots per 16-span) +
//      last-block-per-row threshold.
__global__ void __launch_bounds__(THREADS) k1(const float* __restrict__ rppg,
                                              const float* __restrict__ ppg){
  int s = blockIdx.y;
  const float* __restrict__ x = row_ptr(rppg, ppg, s);
  int tid = threadIdx.x, lane = tid & 31, wid = tid >> 5;
  int p0 = blockIdx.x * TILE + tid * EPT;
  float v[NV]; load_vals(x, p0, v);
  float w[EPT]; window_max(v, w);
  float lsum = 0.f, lps = 0.f;
  int pa = -1, pb = -1, pc = -1, pd = -1;
  float va = 0.f, vb = 0.f, vc = 0.f, vd = 0.f;
  #pragma unroll
  for (int i = 0; i < EPT; i++) {
    float c = v[i + HALF];
    lsum += c;
    if (c == w[i]) {
      lps += c;
      if (pa < 0)      { pa = p0 + i; va = c; }
      else if (pb < 0) { pb = p0 + i; vb = c; }
      else if (pc < 0) { pc = p0 + i; vc = c; }
      else             { pd = p0 + i; vd = c; }
    }
  }
  int np = (pa >= 0) + (pb >= 0) + (pc >= 0) + (pd >= 0);
  // block-wide exclusive prefix of np
  int inc = np;
  #pragma unroll
  for (int off = 1; off < 32; off <<= 1) {
    int t = __shfl_up_sync(FULLM, inc, off);
    if (lane >= off) inc += t;
  }
  int exc = inc - np;
  __shared__ int wsum[8]; __shared__ int wbase[9];
  if (lane == 31) wsum[wid] = inc;
  __syncthreads();
  if (tid == 0) {
    int b = 0;
    #pragma unroll
    for (int ww = 0; ww < 8; ww++) { wbase[ww] = b; b += wsum[ww]; }
    wbase[8] = b;
  }
  __syncthreads();
  int base = wbase[wid] + exc;
  size_t cbase = (size_t)(s*CHUNKS + blockIdx.x) * CAP;
  if (pa >= 0) d_pk[cbase + base]     = make_int2(pa, __float_as_int(va));
  if (pb >= 0) d_pk[cbase + base + 1] = make_int2(pb, __float_as_int(vb));
  if (pc >= 0) d_pk[cbase + base + 2] = make_int2(pc, __float_as_int(vc));
  if (pd >= 0) d_pk[cbase + base + 3] = make_int2(pd, __float_as_int(vd));
  if (tid == 0) d_cnt[s*CHUNKS + blockIdx.x] = wbase[8];
  // stats reduction (sum, peak-sum)
  #pragma unroll
  for (int off = 16; off > 0; off >>= 1) {
    lsum += __shfl_down_sync(FULLM, lsum, off);
    lps  += __shfl_down_sync(FULLM, lps, off);
  }
  __shared__ float sA[8]; __shared__ float sB[8];
  if (lane == 0) { sA[wid] = lsum; sB[wid] = lps; }
  __syncthreads();
  if (tid == 0) {
    float a = 0.f, b = 0.f;
    #pragma unroll
    for (int ww = 0; ww < 8; ww++) { a += sA[ww]; b += sB[ww]; }
    d_p1[s*CHUNKS + blockIdx.x] = make_float2(a, b);
  }
  // ALL block writes (d_pk by every thread, d_p1/d_cnt by tid0) must be done
  // BEFORE the done-counter increment — block barrier first, then fence+atomic.
  __syncthreads();
  __shared__ int amLast;
  if (tid == 0) {
    __threadfence();
    amLast = (atomicAdd(&d_c1[s], 1) == CHUNKS - 1);
  }
  __syncthreads();
  if (amLast) {
    double ls = 0.0, lpsd = 0.0; long long lcc = 0;
    for (int c = tid; c < CHUNKS; c += THREADS) {
      float2 r = d_p1[s*CHUNKS + c];
      ls += (double)r.x; lpsd += (double)r.y; lcc += d_cnt[s*CHUNKS + c];
    }
    #pragma unroll
    for (int off = 16; off > 0; off >>= 1) {
      ls   += __shfl_down_sync(FULLM, ls, off);
      lpsd += __shfl_down_sync(FULLM, lpsd, off);
      lcc  += __shfl_down_sync(FULLM, lcc, off);
    }
    __shared__ double tA[8]; __shared__ double tB[8]; __shared__ long long tC[8];
    if (lane == 0) { tA[wid] = ls; tB[wid] = lpsd; tC[wid] = lcc; }
    __syncthreads();
    if (tid == 0) {
      double a = 0.0, b = 0.0; long long c = 0;
      #pragma unroll
      for (int ww = 0; ww < 8; ww++) { a += tA[ww]; b += tB[ww]; c += tC[ww]; }
      double mu = a / (double)SIG_LEN;
      double mp = b / (double)c;
      d_thr[s] = (float)(0.5 * (mp + mu));
      d_c1[s] = 0;
    }
  }
}

// k2 = pass2: ballot+clz predecessor lookup; IEEE 1/g to match reference terms.
__global__ void __launch_bounds__(THREADS) k2(float* __restrict__ out){
  int s = blockIdx.y;
  int tid = threadIdx.x, lane = tid & 31, wid = tid >> 5;
  int c = blockIdx.x * WPB + wid;
  int rowb = s * CHUNKS;
  float thr = d_thr[s];
  int n = d_cnt[rowb + c];
  const int2* __restrict__ pk = d_pk + (size_t)(rowb + c) * CAP;
  float linv = 0.f; int lpairs = 0; int lfirst = INT_MAX; int carry = -1;
  for (int base = 0; base < n; base += 32) {
    int e = base + lane;
    int pos = -1;
    if (e < n) {
      int2 r = pk[e];
      if (__int_as_float(r.y) > thr) pos = r.x;
    }
    unsigned mask = __ballot_sync(FULLM, pos >= 0);
    unsigned lower = mask & ((1u << lane) - 1u);
    int pl = 31 - __clz(lower);                     // -1 if no lower filtered lane
    int psrc = __shfl_sync(FULLM, pos, pl & 31);
    int prev = (pl >= 0) ? psrc : carry;
    if (pos >= 0) {
      if (prev >= 0) { linv += 1.0f / (float)(pos - prev); lpairs++; }
      lfirst = min(lfirst, pos);
    }
    int hl = 31 - __clz(mask);
    int hsrc = __shfl_sync(FULLM, pos, hl & 31);
    if (hl >= 0) carry = hsrc;                      // uniform across warp
  }
  int blast = carry;
  #pragma unroll
  for (int off = 16; off > 0; off >>= 1) {
    linv   += __shfl_down_sync(FULLM, linv, off);
    lpairs += __shfl_down_sync(FULLM, lpairs, off);
    lfirst  = min(lfirst, __shfl_down_sync(FULLM, lfirst, off));
  }
  if (lane == 0) {
    ChunkRec r;
    r.first = (lfirst == INT_MAX) ? -1 : lfirst;
    r.last  = blast;
    r.inv   = linv;
    r.pairs = lpairs;
    d_rec[rowb + c] = r;
  }
  // CRITICAL: every warp's d_rec write must be complete before this block
  // increments the done-counter — otherwise the last block stitches stale
  // records (the round-7/8 failure). Block barrier, THEN fence+atomic.
  __syncthreads();
  __shared__ int amLast;
  if (tid == 0) {
    __threadfence();
    amLast = (atomicAdd(&d_c2[s], 1) == P2B - 1);
  }
  __syncthreads();
  if (amLast) {
    const int4* rec = reinterpret_cast<const int4*>(d_rec) + (size_t)rowb + (size_t)tid * RPT;
    double sinv = 0.0; int spairs = 0; int sfirst = -1, sprev = -1;
    #pragma unroll
    for (int r = 0; r < RPT; r++) {
      int4 rv = rec[r];
      if (rv.x >= 0) {
        if (sprev >= 0) { sinv += 1.0 / (double)(rv.x - sprev); spairs++; }
        else sfirst = rv.x;
        sprev = rv.y;
      }
      sinv += (double)__int_as_float(rv.z);
      spairs += rv.w;
    }
    int inc2 = sprev;
    #pragma unroll
    for (int off = 1; off < 32; off <<= 1) {
      int t = __shfl_up_sync(FULLM, inc2, off);
      if (lane >= off) inc2 = max(inc2, t);
    }
    int exw = __shfl_up_sync(FULLM, inc2, 1);
    if (lane == 0) exw = -1;
    __shared__ int wmax[8];
    if (lane == 31) wmax[wid] = inc2;
    __syncthreads();
    int wpre = -1;
    for (int ww = 0; ww < wid; ww++) wpre = max(wpre, wmax[ww]);
    int exprev2 = max(exw, wpre);
    if (sfirst >= 0 && exprev2 >= 0) { sinv += 1.0 / (double)(sfirst - exprev2); spairs++; }
    #pragma unroll
    for (int off = 16; off > 0; off >>= 1) {
      sinv   += __shfl_down_sync(FULLM, sinv, off);
      spairs += __shfl_down_sync(FULLM, spairs, off);
    }
    __shared__ double sD[8]; __shared__ int sP[8];
    if (lane == 0) { sD[wid] = sinv; sP[wid] = spairs; }
    __syncthreads();
    if (tid == 0) {
      double dsum = 0.0; int psum = 0;
      #pragma unroll
      for (int ww = 0; ww < 8; ww++) { dsum += sD[ww]; psum += sP[ww]; }
      d_hr[s] = dsum / (double)psum;
      d_c2[s] = 0;
      __threadfence();
      if (atomicAdd(&d_rows, 1) == NROWS - 1) {
        double acc = 0.0;
        #pragma unroll
        for (int i = 0; i < NSIG; i++) {
          double hp = d_hr[NSIG + i];
          double hq = d_hr[i];
          acc += fabs(hp - hq) / hp;
        }
        out[0] = (float)(acc / (double)NSIG);
        d_rows = 0;
      }
    }
  }
}

extern "C" void kernel_launch(void* const* d_in, const int* in_sizes, int n_in,
                              void* d_out, int out_size){
  (void)in_sizes; (void)n_in; (void)out_size;
  const float* rppg = (const float*)d_in[0];
  const float* ppg  = (const float*)d_in[1];
  float* out = (float*)d_out;
  dim3 g1(CHUNKS, NROWS);
  dim3 g2(P2B, NROWS);
  k1<<<g1, THREADS>>>(rppg, ppg);
  k2<<<g2, THREADS>>>(out);
}

// round 10
// speedup vs baseline: 2.6657x; 1.0756x over previous
#include <cuda_runtime.h>
#include <math.h>
#include <limits.h>

#define NSIG 5
#define NROWS 10
#define SIG_LEN 2097152
#define HALF 5
#define THREADS 256
#define EPT 16
#define TILE (THREADS*EPT)        /* 4096 */
#define CHUNKS (SIG_LEN/TILE)     /* 512 */
#define RPT (CHUNKS/THREADS)      /* 2 */
#define CAP 768                   /* >= 683 max peaks; multiple of 128 so the
                                     4-deep unconditional batch loads stay in-bounds */
#define WPB 8                     /* chunks per pass2 block */
#define P2B (CHUNKS/WPB)          /* 64 pass2 blocks per row */
#define NV 26                     /* v[0..25] = x[p0-5 .. p0+20] */
#define FULLM 0xFFFFFFFFu

struct __align__(16) ChunkRec { int first; int last; float inv; int pairs; };

__device__ float2 d_p1[NROWS*CHUNKS];              /* {sum, peak-sum} per chunk */
__device__ float d_thr[NROWS];
__device__ int2 d_pk[(size_t)NROWS*CHUNKS*CAP];
__device__ int d_cnt[NROWS*CHUNKS];
__device__ ChunkRec d_rec[NROWS*CHUNKS];
__device__ double d_hr[NROWS];
__device__ int d_c1[NROWS];       /* zero-init; self-resetting */
__device__ int d_c2[NROWS];
__device__ int d_rows;

static __device__ __forceinline__ float neg_inf() { return __int_as_float(0xff800000); }

__device__ __forceinline__ const float* row_ptr(const float* rppg, const float* ppg, int s){
  return (s < NSIG) ? rppg + (size_t)s*SIG_LEN : ppg + (size_t)(s-NSIG)*SIG_LEN;
}

// v[5..20] = x[p0..p0+15]; halo v[0..4], v[21..25] via neighbor-lane shuffles.
__device__ __forceinline__ void load_vals(const float* __restrict__ x, int p0, float* v){
  #pragma unroll
  for (int q = 0; q < 4; q++) {
    float4 a = *reinterpret_cast<const float4*>(x + p0 + 4*q);
    v[5+4*q] = a.x; v[6+4*q] = a.y; v[7+4*q] = a.z; v[8+4*q] = a.w;
  }
  v[0]  = __shfl_up_sync(FULLM, v[16], 1);
  v[1]  = __shfl_up_sync(FULLM, v[17], 1);
  v[2]  = __shfl_up_sync(FULLM, v[18], 1);
  v[3]  = __shfl_up_sync(FULLM, v[19], 1);
  v[4]  = __shfl_up_sync(FULLM, v[20], 1);
  v[21] = __shfl_down_sync(FULLM, v[5], 1);
  v[22] = __shfl_down_sync(FULLM, v[6], 1);
  v[23] = __shfl_down_sync(FULLM, v[7], 1);
  v[24] = __shfl_down_sync(FULLM, v[8], 1);
  v[25] = __shfl_down_sync(FULLM, v[9], 1);
  int lane = threadIdx.x & 31;
  if (lane == 0) {
    #pragma unroll
    for (int k = 0; k < HALF; k++) {
      int g = p0 - HALF + k;
      v[k] = (g >= 0) ? __ldg(x + g) : neg_inf();
    }
  }
  if (lane == 31) {
    #pragma unroll
    for (int k = 0; k < HALF; k++) {
      int g = p0 + EPT + k;
      v[21+k] = (g < SIG_LEN) ? __ldg(x + g) : neg_inf();
    }
  }
}

// Centered width-11 sliding max for 16 outputs, register max-tree.
__device__ __forceinline__ void window_max(const float* v, float* w){
  float a2[NV-1];
  #pragma unroll
  for (int i = 0; i < NV-1; i++) a2[i] = fmaxf(v[i], v[i+1]);
  float a4[NV-3];
  #pragma unroll
  for (int i = 0; i < NV-3; i++) a4[i] = fmaxf(a2[i], a2[i+2]);
  float a8[NV-7];
  #pragma unroll
  for (int i = 0; i < NV-7; i++) a8[i] = fmaxf(a4[i], a4[i+4]);
  #pragma unroll
  for (int i = 0; i < EPT; i++) w[i] = fmaxf(a8[i], a8[i+3]);  // v[i..i+10]
}

// k1 = pass1 (stats + compact peak lists; 4 scalar slots per 16-span) +
//      last-block-per-row threshold.
__global__ void __launch_bounds__(THREADS) k1(const float* __restrict__ rppg,
                                              const float* __restrict__ ppg){
  int s = blockIdx.y;
  const float* __restrict__ x = row_ptr(rppg, ppg, s);
  int tid = threadIdx.x, lane = tid & 31, wid = tid >> 5;
  int p0 = blockIdx.x * TILE + tid * EPT;
  float v[NV]; load_vals(x, p0, v);
  float w[EPT]; window_max(v, w);
  float lsum = 0.f, lps = 0.f;
  int pa = -1, pb = -1, pc = -1, pd = -1;
  float va = 0.f, vb = 0.f, vc = 0.f, vd = 0.f;
  #pragma unroll
  for (int i = 0; i < EPT; i++) {
    float c = v[i + HALF];
    lsum += c;
    if (c == w[i]) {
      lps += c;
      if (pa < 0)      { pa = p0 + i; va = c; }
      else if (pb < 0) { pb = p0 + i; vb = c; }
      else if (pc < 0) { pc = p0 + i; vc = c; }
      else             { pd = p0 + i; vd = c; }
    }
  }
  int np = (pa >= 0) + (pb >= 0) + (pc >= 0) + (pd >= 0);
  // block-wide exclusive prefix of np
  int inc = np;
  #pragma unroll
  for (int off = 1; off < 32; off <<= 1) {
    int t = __shfl_up_sync(FULLM, inc, off);
    if (lane >= off) inc += t;
  }
  int exc = inc - np;
  __shared__ int wsum[8]; __shared__ int wbase[9];
  if (lane == 31) wsum[wid] = inc;
  __syncthreads();
  if (tid == 0) {
    int b = 0;
    #pragma unroll
    for (int ww = 0; ww < 8; ww++) { wbase[ww] = b; b += wsum[ww]; }
    wbase[8] = b;
  }
  __syncthreads();
  int base = wbase[wid] + exc;
  size_t cbase = (size_t)(s*CHUNKS + blockIdx.x) * CAP;
  if (pa >= 0) d_pk[cbase + base]     = make_int2(pa, __float_as_int(va));
  if (pb >= 0) d_pk[cbase + base + 1] = make_int2(pb, __float_as_int(vb));
  if (pc >= 0) d_pk[cbase + base + 2] = make_int2(pc, __float_as_int(vc));
  if (pd >= 0) d_pk[cbase + base + 3] = make_int2(pd, __float_as_int(vd));
  if (tid == 0) d_cnt[s*CHUNKS + blockIdx.x] = wbase[8];
  // stats reduction (sum, peak-sum)
  #pragma unroll
  for (int off = 16; off > 0; off >>= 1) {
    lsum += __shfl_down_sync(FULLM, lsum, off);
    lps  += __shfl_down_sync(FULLM, lps, off);
  }
  __shared__ float sA[8]; __shared__ float sB[8];
  if (lane == 0) { sA[wid] = lsum; sB[wid] = lps; }
  __syncthreads();
  if (tid == 0) {
    float a = 0.f, b = 0.f;
    #pragma unroll
    for (int ww = 0; ww < 8; ww++) { a += sA[ww]; b += sB[ww]; }
    d_p1[s*CHUNKS + blockIdx.x] = make_float2(a, b);
  }
  // all block writes complete BEFORE done-counter: barrier, then fence+atomic
  __syncthreads();
  __shared__ int amLast;
  if (tid == 0) {
    __threadfence();
    amLast = (atomicAdd(&d_c1[s], 1) == CHUNKS - 1);
  }
  __syncthreads();
  if (amLast) {
    double ls = 0.0, lpsd = 0.0; long long lcc = 0;
    for (int c = tid; c < CHUNKS; c += THREADS) {
      float2 r = d_p1[s*CHUNKS + c];
      ls += (double)r.x; lpsd += (double)r.y; lcc += d_cnt[s*CHUNKS + c];
    }
    #pragma unroll
    for (int off = 16; off > 0; off >>= 1) {
      ls   += __shfl_down_sync(FULLM, ls, off);
      lpsd += __shfl_down_sync(FULLM, lpsd, off);
      lcc  += __shfl_down_sync(FULLM, lcc, off);
    }
    __shared__ double tA[8]; __shared__ double tB[8]; __shared__ long long tC[8];
    if (lane == 0) { tA[wid] = ls; tB[wid] = lpsd; tC[wid] = lcc; }
    __syncthreads();
    if (tid == 0) {
      double a = 0.0, b = 0.0; long long c = 0;
      #pragma unroll
      for (int ww = 0; ww < 8; ww++) { a += tA[ww]; b += tB[ww]; c += tC[ww]; }
      double mu = a / (double)SIG_LEN;
      double mp = b / (double)c;
      d_thr[s] = (float)(0.5 * (mp + mu));
      d_c1[s] = 0;
    }
  }
}

// One 32-entry sub-batch: ballot+clz predecessor lookup, IEEE 1/g.
__device__ __forceinline__ void k2_process(int2 r, int e, int n, float thr, int lane,
                                           float& linv, int& lpairs, int& lfirst, int& carry){
  int pos = (e < n && __int_as_float(r.y) > thr) ? r.x : -1;
  unsigned mask = __ballot_sync(FULLM, pos >= 0);
  unsigned lower = mask & ((1u << lane) - 1u);
  int pl = 31 - __clz(lower);                     // -1 if no lower filtered lane
  int psrc = __shfl_sync(FULLM, pos, pl & 31);
  int prev = (pl >= 0) ? psrc : carry;
  if (pos >= 0) {
    if (prev >= 0) { linv += 1.0f / (float)(pos - prev); lpairs++; }
    lfirst = min(lfirst, pos);
  }
  int hl = 31 - __clz(mask);
  int hsrc = __shfl_sync(FULLM, pos, hl & 31);
  if (hl >= 0) carry = hsrc;                      // uniform across warp
}

// k2 = pass2 with 4-deep load pipelining (MLP=4 instead of serial batches).
__global__ void __launch_bounds__(THREADS) k2(float* __restrict__ out){
  int s = blockIdx.y;
  int tid = threadIdx.x, lane = tid & 31, wid = tid >> 5;
  int c = blockIdx.x * WPB + wid;
  int rowb = s * CHUNKS;
  float thr = d_thr[s];
  int n = d_cnt[rowb + c];
  const int2* __restrict__ pk = d_pk + (size_t)(rowb + c) * CAP;
  float linv = 0.f; int lpairs = 0; int lfirst = INT_MAX; int carry = -1;
  for (int base = 0; base < n; base += 128) {
    // four loads issued back-to-back (always in-bounds: CAP multiple of 128)
    int e0 = base + lane, e1 = e0 + 32, e2 = e0 + 64, e3 = e0 + 96;
    int2 r0 = pk[e0];
    int2 r1 = pk[e1];
    int2 r2 = pk[e2];
    int2 r3 = pk[e3];
    k2_process(r0, e0, n, thr, lane, linv, lpairs, lfirst, carry);
    k2_process(r1, e1, n, thr, lane, linv, lpairs, lfirst, carry);
    k2_process(r2, e2, n, thr, lane, linv, lpairs, lfirst, carry);
    k2_process(r3, e3, n, thr, lane, linv, lpairs, lfirst, carry);
  }
  int blast = carry;
  #pragma unroll
  for (int off = 16; off > 0; off >>= 1) {
    linv   += __shfl_down_sync(FULLM, linv, off);
    lpairs += __shfl_down_sync(FULLM, lpairs, off);
    lfirst  = min(lfirst, __shfl_down_sync(FULLM, lfirst, off));
  }
  if (lane == 0) {
    ChunkRec r;
    r.first = (lfirst == INT_MAX) ? -1 : lfirst;
    r.last  = blast;
    r.inv   = linv;
    r.pairs = lpairs;
    d_rec[rowb + c] = r;
  }
  // every warp's d_rec write must land before the done-counter increment
  __syncthreads();
  __shared__ int amLast;
  if (tid == 0) {
    __threadfence();
    amLast = (atomicAdd(&d_c2[s], 1) == P2B - 1);
  }
  __syncthreads();
  if (amLast) {
    const int4* rec = reinterpret_cast<const int4*>(d_rec) + (size_t)rowb + (size_t)tid * RPT;
    double sinv = 0.0; int spairs = 0; int sfirst = -1, sprev = -1;
    #pragma unroll
    for (int r = 0; r < RPT; r++) {
      int4 rv = rec[r];
      if (rv.x >= 0) {
        if (sprev >= 0) { sinv += 1.0 / (double)(rv.x - sprev); spairs++; }
        else sfirst = rv.x;
        sprev = rv.y;
      }
      sinv += (double)__int_as_float(rv.z);
      spairs += rv.w;
    }
    int inc2 = sprev;
    #pragma unroll
    for (int off = 1; off < 32; off <<= 1) {
      int t = __shfl_up_sync(FULLM, inc2, off);
      if (lane >= off) inc2 = max(inc2, t);
    }
    int exw = __shfl_up_sync(FULLM, inc2, 1);
    if (lane == 0) exw = -1;
    __shared__ int wmax[8];
    if (lane == 31) wmax[wid] = inc2;
    __syncthreads();
    int wpre = -1;
    for (int ww = 0; ww < wid; ww++) wpre = max(wpre, wmax[ww]);
    int exprev2 = max(exw, wpre);
    if (sfirst >= 0 && exprev2 >= 0) { sinv += 1.0 / (double)(sfirst - exprev2); spairs++; }
    #pragma unroll
    for (int off = 16; off > 0; off >>= 1) {
      sinv   += __shfl_down_sync(FULLM, sinv, off);
      spairs += __shfl_down_sync(FULLM, spairs, off);
    }
    __shared__ double sD[8]; __shared__ int sP[8];
    if (lane == 0) { sD[wid] = sinv; sP[wid] = spairs; }
    __syncthreads();
    if (tid == 0) {
      double dsum = 0.0; int psum = 0;
      #pragma unroll
      for (int ww = 0; ww < 8; ww++) { dsum += sD[ww]; psum += sP[ww]; }
      d_hr[s] = dsum / (double)psum;
      d_c2[s] = 0;
      __threadfence();
      if (atomicAdd(&d_rows, 1) == NROWS - 1) {
        double acc = 0.0;
        #pragma unroll
        for (int i = 0; i < NSIG; i++) {
          double hp = d_hr[NSIG + i];
          double hq = d_hr[i];
          acc += fabs(hp - hq) / hp;
        }
        out[0] = (float)(acc / (double)NSIG);
        d_rows = 0;
      }
    }
  }
}

extern "C" void kernel_launch(void* const* d_in, const int* in_sizes, int n_in,
                              void* d_out, int out_size){
  (void)in_sizes; (void)n_in; (void)out_size;
  const float* rppg = (const float*)d_in[0];
  const float* ppg  = (const float*)d_in[1];
  float* out = (float*)d_out;
  dim3 g1(CHUNKS, NROWS);
  dim3 g2(P2B, NROWS);
  k1<<<g1, THREADS>>>(rppg, ppg);
  k2<<<g2, THREADS>>>(out);
}